// round 14
// baseline (speedup 1.0000x reference)
#include <cuda_runtime.h>
#include <cuda_bf16.h>
#include <cstdint>

#define BB   4096      // batch rows
#define SEQ  2048      // sequence length S
#define SU   2056      // u row stride (S + E)
#define OUTW 2057      // out row stride (S + AR + 1)
#define KC   64        // chunk length
#define NCH  32        // chunks per row (SEQ / KC)
#define ORD  9         // recurrence order (AR + 1)
#define EX   8         // exogenous dim
#define BT   128       // threads per block (4 warps)
#define WR   64        // rows per warp (2 per thread, packed f32x2)
#define RPB  256       // rows per block

typedef unsigned long long u64;

// Static device scratch (b-fastest layouts; 8B-aligned for LDG/STG.64)
__device__ __align__(16) float g_v[NCH * ORD * BB];   // [m][k][b]
__device__ __align__(16) float g_s[NCH * ORD * BB];   // [m][k][b]

// ---- packed f32x2 helpers ---------------------------------------------------
__device__ __forceinline__ u64 pk2(float lo, float hi) {
    u64 r; asm("mov.b64 %0, {%1, %2};" : "=l"(r) : "f"(lo), "f"(hi)); return r;
}
__device__ __forceinline__ u64 f2fma(u64 a, u64 b, u64 c) {
    u64 d; asm("fma.rn.f32x2 %0, %1, %2, %3;" : "=l"(d) : "l"(a), "l"(b), "l"(c)); return d;
}
__device__ __forceinline__ u64 f2mul(u64 a, u64 b) {
    u64 d; asm("mul.rn.f32x2 %0, %1, %2;" : "=l"(d) : "l"(a), "l"(b)); return d;
}
__device__ __forceinline__ u64 f2add(u64 a, u64 b) {
    u64 d; asm("add.rn.f32x2 %0, %1, %2;" : "=l"(d) : "l"(a), "l"(b)); return d;
}

__device__ __forceinline__ void load_a(const float* __restrict__ W, float* a) {
    a[0] = -__ldg(&W[0]);
    #pragma unroll
    for (int k = 1; k < 8; k++) a[k] = __ldg(&W[k - 1]) - __ldg(&W[k]);
    a[8] = 1.0f + __ldg(&W[7]);
}

__device__ __forceinline__ void load_coefs_packed(const float* __restrict__ W,
                                                  u64* a2, u64* wu2) {
    float a[ORD];
    load_a(W, a);
    #pragma unroll
    for (int k = 0; k < ORD; k++) a2[k] = pk2(a[k], a[k]);
    #pragma unroll
    for (int e = 0; e < EX; e++) { float v = __ldg(&W[8 + e]); wu2[e] = pk2(v, v); }
}

// One packed recurrence step (2 rows), tree form (proven in r10).
__device__ __forceinline__ u64 step_packed(const u64* a2, const u64* wu2,
                                           const u64* uw, const u64* w, int j) {
    u64 q0 = f2mul(wu2[0], uw[(0 + j) % 9]);
    u64 q1 = f2mul(wu2[2], uw[(2 + j) % 9]);
    u64 q2 = f2mul(wu2[4], uw[(4 + j) % 9]);
    u64 q3 = f2mul(wu2[6], uw[(6 + j) % 9]);
    q0 = f2fma(wu2[1], uw[(1 + j) % 9], q0);
    q1 = f2fma(wu2[3], uw[(3 + j) % 9], q1);
    q2 = f2fma(wu2[5], uw[(5 + j) % 9], q2);
    q3 = f2fma(wu2[7], uw[(7 + j) % 9], q3);
    u64 c = f2add(f2add(q0, q1), f2add(q2, q3));

    u64 c0 = f2fma(a2[0], w[(0 + j) % 9], c);
    u64 c1 = f2mul(a2[1], w[(1 + j) % 9]);
    u64 c2 = f2mul(a2[2], w[(2 + j) % 9]);
    u64 c3 = f2mul(a2[3], w[(3 + j) % 9]);
    c0 = f2fma(a2[4], w[(4 + j) % 9], c0);
    c1 = f2fma(a2[5], w[(5 + j) % 9], c1);
    c2 = f2fma(a2[6], w[(6 + j) % 9], c2);
    c3 = f2fma(a2[7], w[(7 + j) % 9], c3);
    u64 x = f2add(f2add(c0, c1), f2add(c2, c3));
    return f2fma(a2[8], w[(8 + j) % 9], x);
}

__device__ __forceinline__ void cpa4(void* smem, const void* gmem) {
    unsigned int d = (unsigned int)__cvta_generic_to_shared(smem);
    asm volatile("cp.async.ca.shared.global [%0], [%1], 4;" :: "r"(d), "l"(gmem));
}
#define CP_COMMIT() asm volatile("cp.async.commit_group;" ::: "memory")
#define CP_WAIT1()  asm volatile("cp.async.wait_group 1;" ::: "memory")
#define CP_WAIT0()  asm volatile("cp.async.wait_group 0;" ::: "memory")

// Warp-local ring load: stage-phase q covers global cols [8q-1, 8q+7) of this
// warp's 64 rows into su[q%3][lc][r]. ubase = &u[b0w][m*64] (so col gc maps to
// ubase + r*SU + 8q + lc, since 1 + gc = 8q + lc). 32B-aligned gmem segments.
#define LOAD_PHASE(q) do {                                                    \
    _Pragma("unroll")                                                         \
    for (int i = 0; i < 16; i++) {                                            \
        int e = i * 32 + t;                                                   \
        int r = e >> 3;                                                       \
        int lc = e & 7;                                                       \
        cpa4(&su[(q) % 3][lc][r], ubase + (size_t)r * SU + ((q) * 8 + lc));   \
    }                                                                         \
    CP_COMMIT();                                                              \
} while (0)

// ---------------------------------------------------------------------------
// Kernel 1 (cv): zero-state recurrence, packed 2 rows/thread, warp-local
// 3-slot cp.async ring (no block barriers). Emits final 9-window to g_v.
// ---------------------------------------------------------------------------
__global__ void __launch_bounds__(BT) cv_kernel(const float* __restrict__ u,
                                                const float* __restrict__ W) {
    __shared__ float su_all[4][3][8][66];
    int m  = blockIdx.x >> 4;
    int b0 = (blockIdx.x & 15) * RPB;
    int wid = threadIdx.x >> 5;
    int t   = threadIdx.x & 31;
    int b0w = b0 + wid * WR;
    float (*su)[8][66] = su_all[wid];
    const float* ubase = u + (size_t)b0w * SU + m * KC;

    LOAD_PHASE(0); LOAD_PHASE(1); LOAD_PHASE(2);

    u64 a2[ORD], wu2[EX];
    load_coefs_packed(W, a2, wu2);

    CP_WAIT1();            // stages 0,1 resident
    __syncwarp();

    u64 w9[ORD], uw[ORD];
    u64 z = pk2(0.0f, 0.0f);
    #pragma unroll
    for (int k = 0; k < ORD; k++) {
        int q = (k + 1) / 8, lc = (k + 1) - 8 * q;     // col k -> stage q
        uw[k] = *(const u64*)&su[q][lc][2 * t];
        w9[k] = z;
    }

    #pragma unroll
    for (int p = 0; p < 8; p++) {
        if (p <= 5) { LOAD_PHASE(p + 3); CP_WAIT1(); } else { CP_WAIT0(); }
        __syncwarp();
        #pragma unroll
        for (int jj = 0; jj < 8; jj++) {
            int j = p * 8 + jj;
            u64 x = step_packed(a2, wu2, uw, w9, j);
            if (j <= 61) {
                int q = (j + 10) / 8, lc = (j + 10) - 8 * q;   // col j+9
                uw[j % 9] = *(const u64*)&su[q % 3][lc][2 * t];
            }
            w9[j % 9] = x;
        }
    }

    #pragma unroll
    for (int k = 0; k < ORD; k++)
        *(u64*)&g_v[((size_t)m * ORD + k) * BB + b0w + 2 * t] = w9[(k + KC) % 9];
}

// ---------------------------------------------------------------------------
// Kernel 2 (states): unchanged (r7): M = A^K via lane recurrences + shfl,
// 31-step chain with 2-deep v prefetch. out[b][0..8] = y.
// ---------------------------------------------------------------------------
__global__ void __launch_bounds__(32) states_kernel(const float* __restrict__ W,
                                                    const float* __restrict__ y,
                                                    float* __restrict__ out) {
    int lane = threadIdx.x;
    int b = blockIdx.x * 32 + lane;

    float a[ORD];
    load_a(W, a);

    float w[ORD];
    #pragma unroll
    for (int k = 0; k < ORD; k++) w[k] = (k == lane) ? 1.0f : 0.0f;
    #pragma unroll
    for (int p = 0; p < KC; p++) {
        float z = 0.0f;
        #pragma unroll
        for (int k = 0; k < ORD; k++) z += a[k] * w[(k + p) % 9];
        w[p % 9] = z;
    }
    float MT[ORD * ORD];
    #pragma unroll
    for (int r = 0; r < ORD; r++)
        #pragma unroll
        for (int k = 0; k < ORD; k++)
            MT[r * ORD + k] = __shfl_sync(0xffffffffu, w[(k + KC) % 9], r);

    float s[ORD];
    #pragma unroll
    for (int k = 0; k < ORD; k++) {
        s[k] = y[(size_t)b * ORD + k];
        out[(size_t)b * OUTW + k] = s[k];
        g_s[(size_t)k * BB + b] = s[k];
    }

    float va[ORD], vb[ORD];
    #pragma unroll
    for (int k = 0; k < ORD; k++) va[k] = g_v[(size_t)k * BB + b];
    #pragma unroll
    for (int k = 0; k < ORD; k++) vb[k] = g_v[((size_t)ORD + k) * BB + b];

    #pragma unroll
    for (int m = 0; m < NCH - 1; m++) {
        float ns[ORD];
        #pragma unroll
        for (int k = 0; k < ORD; k++) ns[k] = va[k];
        #pragma unroll
        for (int k = 0; k < ORD; k++) va[k] = vb[k];
        if (m + 2 <= NCH - 2) {
            const float* gv = g_v + ((size_t)(m + 2) * ORD) * BB + b;
            #pragma unroll
            for (int k = 0; k < ORD; k++) vb[k] = gv[(size_t)k * BB];
        }
        #pragma unroll
        for (int r = 0; r < ORD; r++) {
            float sr = s[r];
            #pragma unroll
            for (int k = 0; k < ORD; k++) ns[k] += MT[r * ORD + k] * sr;
        }
        float* gs = g_s + ((size_t)(m + 1) * ORD) * BB + b;
        #pragma unroll
        for (int k = 0; k < ORD; k++) { s[k] = ns[k]; gs[(size_t)k * BB] = s[k]; }
    }
}

// ---------------------------------------------------------------------------
// Kernel 3 (pass2): true-state replay, packed 2 rows/thread, same warp-local
// ring; 8-step per-warp smem staging then transposed coalesced out flush.
// ---------------------------------------------------------------------------
__global__ void __launch_bounds__(BT) pass2_kernel(const float* __restrict__ u,
                                                   const float* __restrict__ W,
                                                   float* __restrict__ out) {
    __shared__ float su_all[4][3][8][66];
    __shared__ float sb_all[4][8][66];
    int m  = blockIdx.x >> 4;
    int b0 = (blockIdx.x & 15) * RPB;
    int wid = threadIdx.x >> 5;
    int t   = threadIdx.x & 31;
    int b0w = b0 + wid * WR;
    float (*su)[8][66] = su_all[wid];
    float (*sb)[66]    = sb_all[wid];
    const float* ubase = u + (size_t)b0w * SU + m * KC;

    LOAD_PHASE(0); LOAD_PHASE(1); LOAD_PHASE(2);

    u64 a2[ORD], wu2[EX];
    load_coefs_packed(W, a2, wu2);

    u64 w9[ORD], uw[ORD];
    #pragma unroll
    for (int k = 0; k < ORD; k++)
        w9[k] = *(const u64*)&g_s[((size_t)m * ORD + k) * BB + b0w + 2 * t];

    CP_WAIT1();
    __syncwarp();
    #pragma unroll
    for (int k = 0; k < ORD; k++) {
        int q = (k + 1) / 8, lc = (k + 1) - 8 * q;
        uw[k] = *(const u64*)&su[q][lc][2 * t];
    }

    int obase = ORD + m * KC;

    #pragma unroll
    for (int p = 0; p < 8; p++) {
        if (p <= 5) { LOAD_PHASE(p + 3); CP_WAIT1(); } else { CP_WAIT0(); }
        __syncwarp();
        #pragma unroll
        for (int jj = 0; jj < 8; jj++) {
            int j = p * 8 + jj;
            u64 x = step_packed(a2, wu2, uw, w9, j);
            if (j <= 61) {
                int q = (j + 10) / 8, lc = (j + 10) - 8 * q;
                uw[j % 9] = *(const u64*)&su[q % 3][lc][2 * t];
            }
            w9[j % 9] = x;
            *(u64*)&sb[jj][2 * t] = x;
        }
        __syncwarp();
        // Flush 8 steps x 64 rows, transposed: warp writes 32B row segments.
        #pragma unroll
        for (int i = 0; i < 16; i++) {
            int e = i * 32 + t;
            int r  = e >> 3;
            int cc = e & 7;
            out[(size_t)(b0w + r) * OUTW + obase + p * 8 + cc] = sb[cc][r];
        }
        __syncwarp();
    }
}

// ---------------------------------------------------------------------------
extern "C" void kernel_launch(void* const* d_in, const int* in_sizes, int n_in,
                              void* d_out, int out_size) {
    const float* y = (const float*)d_in[0];
    const float* u = (const float*)d_in[1];
    const float* W = (const float*)d_in[2];
    for (int i = 0; i < n_in; i++) {
        if (in_sizes[i] == BB * ORD)      y = (const float*)d_in[i];
        else if (in_sizes[i] == BB * SU)  u = (const float*)d_in[i];
        else if (in_sizes[i] == 16)       W = (const float*)d_in[i];
    }
    float* out = (float*)d_out;

    cudaFuncSetAttribute(cv_kernel,    cudaFuncAttributePreferredSharedMemoryCarveout, 100);
    cudaFuncSetAttribute(pass2_kernel, cudaFuncAttributePreferredSharedMemoryCarveout, 100);

    cv_kernel<<<NCH * (BB / RPB), BT>>>(u, W);      // 512 x 128
    states_kernel<<<BB / 32, 32>>>(W, y, out);      // 128 x 32
    pass2_kernel<<<NCH * (BB / RPB), BT>>>(u, W, out);
}

// round 15
// speedup vs baseline: 1.5514x; 1.5514x over previous
#include <cuda_runtime.h>
#include <cuda_bf16.h>
#include <cstdint>

#define BB   4096      // batch rows
#define SEQ  2048      // sequence length S
#define SU   2056      // u row stride (S + E)
#define OUTW 2057      // out row stride (S + AR + 1)
#define KC   64        // chunk length
#define NCH  32        // chunks per row (SEQ / KC)
#define ORD  9         // recurrence order (AR + 1)
#define EX   8         // exogenous dim
#define BT   128       // threads per block in the two big passes

// Static device scratch (b-fastest layouts, coalesced for lane = b)
__device__ float g_v[NCH * ORD * BB];      // [m][k][b] zero-state final windows
__device__ float g_s[NCH * ORD * BB];      // [m][k][b] true boundary states

__device__ __forceinline__ void load_a(const float* __restrict__ W, float* a) {
    a[0] = -__ldg(&W[0]);
    #pragma unroll
    for (int k = 1; k < 8; k++) a[k] = __ldg(&W[k - 1]) - __ldg(&W[k]);
    a[8] = 1.0f + __ldg(&W[7]);
}

// One recurrence step, TREE form (proven best in r5/r7). 17 FMA-class ops.
__device__ __forceinline__ float step_rec(const float* a, const float* wu,
                                          const float* uw, const float* w, int j) {
    float e0 = wu[0] * uw[(0 + j) % 9] + wu[1] * uw[(1 + j) % 9];
    float e1 = wu[2] * uw[(2 + j) % 9] + wu[3] * uw[(3 + j) % 9];
    float e2 = wu[4] * uw[(4 + j) % 9] + wu[5] * uw[(5 + j) % 9];
    float e3 = wu[6] * uw[(6 + j) % 9] + wu[7] * uw[(7 + j) % 9];
    float c  = (e0 + e1) + (e2 + e3);
    float s0 = c + a[0] * w[(0 + j) % 9];
    float s1 = a[1] * w[(1 + j) % 9] + a[2] * w[(2 + j) % 9];
    float s2 = a[3] * w[(3 + j) % 9] + a[4] * w[(4 + j) % 9];
    float s3 = a[5] * w[(5 + j) % 9] + a[6] * w[(6 + j) % 9];
    float x  = ((s0 + s1) + (s2 + s3)) + a[7] * w[(7 + j) % 9];
    return fmaf(a[8], w[(8 + j) % 9], x);
}

__device__ __forceinline__ void cpa4(void* smem, const void* gmem) {
    unsigned int d = (unsigned int)__cvta_generic_to_shared(smem);
    asm volatile("cp.async.ca.shared.global [%0], [%1], 4;" :: "r"(d), "l"(gmem));
}
#define CP_COMMIT() asm volatile("cp.async.commit_group;" ::: "memory")
#define CP_WAIT1()  asm volatile("cp.async.wait_group 1;" ::: "memory")
#define CP_WAIT0()  asm volatile("cp.async.wait_group 0;" ::: "memory")

// Phase q (q=0..3): u-offsets [16q, 16q+16) of each of the block's 128 rows
// into su[slot][lc][r]. ubase = &u[b0][m*64]; offsets 64B-aligned.
// GMEM: per warp 2 rows x 16 consecutive floats (64B segments).
// SMEM read path su[s][lc][tid]: consecutive tid -> conflict-free.
#define LOAD_PH(q, slot) do {                                                  \
    _Pragma("unroll")                                                          \
    for (int i = 0; i < 16; i++) {                                             \
        int e = i * BT + tid;                                                  \
        int r = e >> 4, lc = e & 15;                                           \
        cpa4(&su[slot][lc][r], ubase + (size_t)r * SU + ((q) * 16 + lc));      \
    }                                                                          \
    CP_COMMIT();                                                               \
} while (0)

// Phase 4: u-offsets [64, 72), 8 cols.
#define LOAD_PH4(slot) do {                                                    \
    _Pragma("unroll")                                                          \
    for (int i = 0; i < 8; i++) {                                              \
        int e = i * BT + tid;                                                  \
        int r = e >> 3, lc = e & 7;                                            \
        cpa4(&su[slot][lc][r], ubase + (size_t)r * SU + (64 + lc));            \
    }                                                                          \
    CP_COMMIT();                                                               \
} while (0)

// Refill map: step j consumes logical c-col j+9 = u-offset j+10.
//   j in [0,5]   -> phase 0 (slot 0), lc = j+10
//   j in [6,21]  -> phase 1 (slot 1), lc = j-6
//   j in [22,37] -> phase 2 (slot 0), lc = j-22
//   j in [38,53] -> phase 3 (slot 1), lc = j-38
//   j in [54,61] -> phase 4 (slot 0), lc = j-54
// Init window: logical cols 0..8 = u-offsets 1..9 -> phase 0, lc = k+1.

// ---------------------------------------------------------------------------
// Kernel 1 (cv): zero-state recurrence; double-buffered cp.async ring so each
// phase's load is in flight during the previous 16-step compute segment.
// ---------------------------------------------------------------------------
__global__ void __launch_bounds__(BT) cv_kernel(const float* __restrict__ u,
                                                const float* __restrict__ W) {
    __shared__ float su[2][16][130];
    int m  = blockIdx.x >> 5;
    int b0 = (blockIdx.x & 31) * BT;
    int tid = threadIdx.x;
    const float* ubase = u + (size_t)b0 * SU + m * KC;

    LOAD_PH(0, 0);
    LOAD_PH(1, 1);

    float a[ORD], wu[EX];
    load_a(W, a);
    #pragma unroll
    for (int e = 0; e < EX; e++) wu[e] = __ldg(&W[8 + e]);

    CP_WAIT1();             // P0 resident
    __syncthreads();

    float w[ORD], uw[ORD];
    #pragma unroll
    for (int k = 0; k < ORD; k++) { w[k] = 0.0f; uw[k] = su[0][k + 1][tid]; }

    #pragma unroll
    for (int j = 0; j < 6; j++) {                    // refills phase 0 (slot 0)
        float x = step_rec(a, wu, uw, w, j);
        uw[j % 9] = su[0][j + 10][tid];
        w[j % 9] = x;
    }

    CP_WAIT0(); __syncthreads();                     // P1 resident; slot 0 free
    LOAD_PH(2, 0);                                   // P2 overlaps steps 6..21
    #pragma unroll
    for (int j = 6; j < 22; j++) {                   // refills phase 1 (slot 1)
        float x = step_rec(a, wu, uw, w, j);
        uw[j % 9] = su[1][j - 6][tid];
        w[j % 9] = x;
    }

    CP_WAIT0(); __syncthreads();                     // P2 resident; slot 1 free
    LOAD_PH(3, 1);                                   // P3 overlaps steps 22..37
    #pragma unroll
    for (int j = 22; j < 38; j++) {                  // refills phase 2 (slot 0)
        float x = step_rec(a, wu, uw, w, j);
        uw[j % 9] = su[0][j - 22][tid];
        w[j % 9] = x;
    }

    CP_WAIT0(); __syncthreads();                     // P3 resident; slot 0 free
    LOAD_PH4(0);                                     // P4 overlaps steps 38..53
    #pragma unroll
    for (int j = 38; j < 54; j++) {                  // refills phase 3 (slot 1)
        float x = step_rec(a, wu, uw, w, j);
        uw[j % 9] = su[1][j - 38][tid];
        w[j % 9] = x;
    }

    CP_WAIT0(); __syncthreads();                     // P4 resident
    #pragma unroll
    for (int j = 54; j < KC; j++) {                  // refills phase 4 (slot 0)
        float x = step_rec(a, wu, uw, w, j);
        if (j <= 61) uw[j % 9] = su[0][j - 54][tid];
        w[j % 9] = x;
    }

    float* gv = g_v + ((size_t)m * ORD) * BB + b0 + tid;
    #pragma unroll
    for (int k = 0; k < ORD; k++) gv[(size_t)k * BB] = w[(k + KC) % 9];
}

// ---------------------------------------------------------------------------
// Kernel 2 (states): unchanged (r7). M = A^K via lane recurrences + shfl;
// 31-step boundary chain with 2-deep v prefetch. out[b][0..8] = y.
// ---------------------------------------------------------------------------
__global__ void __launch_bounds__(32) states_kernel(const float* __restrict__ W,
                                                    const float* __restrict__ y,
                                                    float* __restrict__ out) {
    int lane = threadIdx.x;
    int b = blockIdx.x * 32 + lane;

    float a[ORD];
    load_a(W, a);

    float w[ORD];
    #pragma unroll
    for (int k = 0; k < ORD; k++) w[k] = (k == lane) ? 1.0f : 0.0f;
    #pragma unroll
    for (int p = 0; p < KC; p++) {
        float z = 0.0f;
        #pragma unroll
        for (int k = 0; k < ORD; k++) z += a[k] * w[(k + p) % 9];
        w[p % 9] = z;
    }
    float MT[ORD * ORD];
    #pragma unroll
    for (int r = 0; r < ORD; r++)
        #pragma unroll
        for (int k = 0; k < ORD; k++)
            MT[r * ORD + k] = __shfl_sync(0xffffffffu, w[(k + KC) % 9], r);

    float s[ORD];
    #pragma unroll
    for (int k = 0; k < ORD; k++) {
        s[k] = y[(size_t)b * ORD + k];
        out[(size_t)b * OUTW + k] = s[k];
        g_s[(size_t)k * BB + b] = s[k];
    }

    float va[ORD], vb[ORD];
    #pragma unroll
    for (int k = 0; k < ORD; k++) va[k] = g_v[(size_t)k * BB + b];
    #pragma unroll
    for (int k = 0; k < ORD; k++) vb[k] = g_v[((size_t)ORD + k) * BB + b];

    #pragma unroll
    for (int m = 0; m < NCH - 1; m++) {
        float ns[ORD];
        #pragma unroll
        for (int k = 0; k < ORD; k++) ns[k] = va[k];
        #pragma unroll
        for (int k = 0; k < ORD; k++) va[k] = vb[k];
        if (m + 2 <= NCH - 2) {
            const float* gv = g_v + ((size_t)(m + 2) * ORD) * BB + b;
            #pragma unroll
            for (int k = 0; k < ORD; k++) vb[k] = gv[(size_t)k * BB];
        }
        #pragma unroll
        for (int r = 0; r < ORD; r++) {
            float sr = s[r];
            #pragma unroll
            for (int k = 0; k < ORD; k++) ns[k] += MT[r * ORD + k] * sr;
        }
        float* gs = g_s + ((size_t)(m + 1) * ORD) * BB + b;
        #pragma unroll
        for (int k = 0; k < ORD; k++) { s[k] = ns[k]; gs[(size_t)k * BB] = s[k]; }
    }
}

// Flush 16 staged steps to out in coalesced 64B row segments.
#define FLUSH16(j) do {                                                        \
    __syncthreads();                                                           \
    int jj = (j) & ~15;                                                        \
    _Pragma("unroll")                                                          \
    for (int q = 0; q < 16; q++) {                                             \
        int e  = q * BT + tid;                                                 \
        int tp = e & 15;                                                       \
        int bp = e >> 4;                                                       \
        out[(size_t)(b0 + bp) * OUTW + ocol0 + jj + tp] = sb[tp][bp];          \
    }                                                                          \
    __syncthreads();                                                           \
} while (0)

// ---------------------------------------------------------------------------
// Kernel 3 (pass2): true-state replay with the same cp.async ring; 16-step
// smem staging + coalesced out flush (r7 path).
// ---------------------------------------------------------------------------
__global__ void __launch_bounds__(BT) pass2_kernel(const float* __restrict__ u,
                                                   const float* __restrict__ W,
                                                   float* __restrict__ out) {
    __shared__ float su[2][16][130];
    __shared__ float sb[16][BT + 1];
    int m  = blockIdx.x >> 5;
    int b0 = (blockIdx.x & 31) * BT;
    int tid = threadIdx.x;
    int ocol0 = ORD + m * KC;
    const float* ubase = u + (size_t)b0 * SU + m * KC;

    LOAD_PH(0, 0);
    LOAD_PH(1, 1);

    float a[ORD], wu[EX];
    load_a(W, a);
    #pragma unroll
    for (int e = 0; e < EX; e++) wu[e] = __ldg(&W[8 + e]);

    float w[ORD], uw[ORD];
    const float* gs = g_s + ((size_t)m * ORD) * BB + b0 + tid;
    #pragma unroll
    for (int k = 0; k < ORD; k++) w[k] = gs[(size_t)k * BB];

    CP_WAIT1();
    __syncthreads();
    #pragma unroll
    for (int k = 0; k < ORD; k++) uw[k] = su[0][k + 1][tid];

    #pragma unroll
    for (int j = 0; j < 6; j++) {
        float x = step_rec(a, wu, uw, w, j);
        uw[j % 9] = su[0][j + 10][tid];
        w[j % 9] = x;
        sb[j & 15][tid] = x;
    }

    CP_WAIT0(); __syncthreads();
    LOAD_PH(2, 0);
    #pragma unroll
    for (int j = 6; j < 22; j++) {
        float x = step_rec(a, wu, uw, w, j);
        uw[j % 9] = su[1][j - 6][tid];
        w[j % 9] = x;
        sb[j & 15][tid] = x;
        if ((j & 15) == 15) FLUSH16(j);
    }

    CP_WAIT0(); __syncthreads();
    LOAD_PH(3, 1);
    #pragma unroll
    for (int j = 22; j < 38; j++) {
        float x = step_rec(a, wu, uw, w, j);
        uw[j % 9] = su[0][j - 22][tid];
        w[j % 9] = x;
        sb[j & 15][tid] = x;
        if ((j & 15) == 15) FLUSH16(j);
    }

    CP_WAIT0(); __syncthreads();
    LOAD_PH4(0);
    #pragma unroll
    for (int j = 38; j < 54; j++) {
        float x = step_rec(a, wu, uw, w, j);
        uw[j % 9] = su[1][j - 38][tid];
        w[j % 9] = x;
        sb[j & 15][tid] = x;
        if ((j & 15) == 15) FLUSH16(j);
    }

    CP_WAIT0(); __syncthreads();
    #pragma unroll
    for (int j = 54; j < KC; j++) {
        float x = step_rec(a, wu, uw, w, j);
        if (j <= 61) uw[j % 9] = su[0][j - 54][tid];
        w[j % 9] = x;
        sb[j & 15][tid] = x;
        if ((j & 15) == 15) FLUSH16(j);
    }
}

// ---------------------------------------------------------------------------
extern "C" void kernel_launch(void* const* d_in, const int* in_sizes, int n_in,
                              void* d_out, int out_size) {
    const float* y = (const float*)d_in[0];
    const float* u = (const float*)d_in[1];
    const float* W = (const float*)d_in[2];
    for (int i = 0; i < n_in; i++) {
        if (in_sizes[i] == BB * ORD)      y = (const float*)d_in[i];
        else if (in_sizes[i] == BB * SU)  u = (const float*)d_in[i];
        else if (in_sizes[i] == 16)       W = (const float*)d_in[i];
    }
    float* out = (float*)d_out;

    cudaFuncSetAttribute(cv_kernel,    cudaFuncAttributePreferredSharedMemoryCarveout, 100);
    cudaFuncSetAttribute(pass2_kernel, cudaFuncAttributePreferredSharedMemoryCarveout, 100);

    cv_kernel<<<NCH * (BB / BT), BT>>>(u, W);       // 1024 x 128
    states_kernel<<<BB / 32, 32>>>(W, y, out);      // 128 x 32
    pass2_kernel<<<NCH * (BB / BT), BT>>>(u, W, out);
}

// round 16
// speedup vs baseline: 1.5526x; 1.0008x over previous
#include <cuda_runtime.h>
#include <cuda_bf16.h>
#include <cstdint>

#define BB   4096      // batch rows
#define SEQ  2048      // sequence length S
#define SU   2056      // u row stride (S + E)
#define OUTW 2057      // out row stride (S + AR + 1)
#define KC   64        // chunk length
#define NCH  32        // chunks per row (SEQ / KC)
#define ORD  9         // recurrence order (AR + 1)
#define EX   8         // exogenous dim
#define BT   128       // threads per block in the two big passes

// Static device scratch (b-fastest layouts, coalesced for lane = b)
__device__ float g_v[NCH * ORD * BB];      // [m][k][b] zero-state final windows
__device__ float g_s[NCH * ORD * BB];      // [m][k][b] true boundary states

__device__ __forceinline__ void load_a(const float* __restrict__ W, float* a) {
    a[0] = -__ldg(&W[0]);
    #pragma unroll
    for (int k = 1; k < 8; k++) a[k] = __ldg(&W[k - 1]) - __ldg(&W[k]);
    a[8] = 1.0f + __ldg(&W[7]);
}

// One recurrence step, TREE form (proven best). 17 FMA-class ops,
// compile-time rotation; a8*x_prev last -> 4-cyc cross-step chain.
__device__ __forceinline__ float step_rec(const float* a, const float* wu,
                                          const float* uw, const float* w, int j) {
    float e0 = wu[0] * uw[(0 + j) % 9] + wu[1] * uw[(1 + j) % 9];
    float e1 = wu[2] * uw[(2 + j) % 9] + wu[3] * uw[(3 + j) % 9];
    float e2 = wu[4] * uw[(4 + j) % 9] + wu[5] * uw[(5 + j) % 9];
    float e3 = wu[6] * uw[(6 + j) % 9] + wu[7] * uw[(7 + j) % 9];
    float c  = (e0 + e1) + (e2 + e3);
    float s0 = c + a[0] * w[(0 + j) % 9];
    float s1 = a[1] * w[(1 + j) % 9] + a[2] * w[(2 + j) % 9];
    float s2 = a[3] * w[(3 + j) % 9] + a[4] * w[(4 + j) % 9];
    float s3 = a[5] * w[(5 + j) % 9] + a[6] * w[(6 + j) % 9];
    float x  = ((s0 + s1) + (s2 + s3)) + a[7] * w[(7 + j) % 9];
    return fmaf(a[8], w[(8 + j) % 9], x);
}

// Cooperative phased tile load: cols [c0, c0+38] of 128 u-rows into su.
__device__ __forceinline__ void load_utile(const float* __restrict__ u,
                                           float su[BT][41],
                                           int b0, int m, int c0,
                                           int lane, int wr) {
    #pragma unroll
    for (int r = wr; r < BT; r += 4) {
        const float* ur = u + (size_t)(b0 + r) * SU + 1 + m * KC + c0;
        su[r][lane] = ur[lane];
        if (lane < 7) su[r][lane + 32] = ur[lane + 32];
    }
}

// ---------------------------------------------------------------------------
// Kernel 1 (cv): zero-state recurrence per (chunk m, row b); 64 steps in two
// 32-step phases (21 KB smem). Emits final 9-window to g_v[m][k][b].
// (r7-verbatim: the proven best variant.)
// ---------------------------------------------------------------------------
__global__ void __launch_bounds__(BT) cv_kernel(const float* __restrict__ u,
                                                const float* __restrict__ W) {
    __shared__ float su[BT][41];           // stride 41: gcd(41,32)=1, conflict-free
    int m  = blockIdx.x >> 5;
    int b0 = (blockIdx.x & 31) * BT;
    int tid = threadIdx.x;
    int lane = tid & 31, wr = tid >> 5;

    float a[ORD], wu[EX];
    load_a(W, a);
    #pragma unroll
    for (int e = 0; e < EX; e++) wu[e] = __ldg(&W[8 + e]);

    // Phase A: cols 0..38
    load_utile(u, su, b0, m, 0, lane, wr);
    __syncthreads();

    float w[ORD], uw[ORD];
    #pragma unroll
    for (int k = 0; k < ORD; k++) { w[k] = 0.0f; uw[k] = su[tid][k]; }

    #pragma unroll
    for (int j = 0; j < 32; j++) {
        float x = step_rec(a, wu, uw, w, j);
        if (j <= 29) uw[j % 9] = su[tid][j + 9];   // cols 9..38
        w[j % 9] = x;
    }
    __syncthreads();

    // Phase B: cols 32..70 at su[tid][cc-32]
    load_utile(u, su, b0, m, 32, lane, wr);
    __syncthreads();
    uw[30 % 9] = su[tid][7];   // col 39 (deferred refill of step 30)
    uw[31 % 9] = su[tid][8];   // col 40 (deferred refill of step 31)

    #pragma unroll
    for (int j = 32; j < KC; j++) {
        float x = step_rec(a, wu, uw, w, j);
        if (j <= 61) uw[j % 9] = su[tid][j - 23];  // col j+9
        w[j % 9] = x;
    }

    float* gv = g_v + ((size_t)m * ORD) * BB + b0 + tid;
    #pragma unroll
    for (int k = 0; k < ORD; k++) gv[(size_t)k * BB] = w[(k + KC) % 9];
}

// ---------------------------------------------------------------------------
// Kernel 2 (states): M = A^K in registers via lane recurrences + shfl;
// 31-step boundary chain with 2-deep v prefetch. out[b][0..8] = y.
// ---------------------------------------------------------------------------
__global__ void __launch_bounds__(32) states_kernel(const float* __restrict__ W,
                                                    const float* __restrict__ y,
                                                    float* __restrict__ out) {
    int lane = threadIdx.x;
    int b = blockIdx.x * 32 + lane;

    float a[ORD];
    load_a(W, a);

    float w[ORD];
    #pragma unroll
    for (int k = 0; k < ORD; k++) w[k] = (k == lane) ? 1.0f : 0.0f;
    #pragma unroll
    for (int p = 0; p < KC; p++) {
        float z = 0.0f;
        #pragma unroll
        for (int k = 0; k < ORD; k++) z += a[k] * w[(k + p) % 9];
        w[p % 9] = z;
    }
    float MT[ORD * ORD];
    #pragma unroll
    for (int r = 0; r < ORD; r++)
        #pragma unroll
        for (int k = 0; k < ORD; k++)
            MT[r * ORD + k] = __shfl_sync(0xffffffffu, w[(k + KC) % 9], r);

    float s[ORD];
    #pragma unroll
    for (int k = 0; k < ORD; k++) {
        s[k] = y[(size_t)b * ORD + k];
        out[(size_t)b * OUTW + k] = s[k];
        g_s[(size_t)k * BB + b] = s[k];
    }

    float va[ORD], vb[ORD];
    #pragma unroll
    for (int k = 0; k < ORD; k++) va[k] = g_v[(size_t)k * BB + b];
    #pragma unroll
    for (int k = 0; k < ORD; k++) vb[k] = g_v[((size_t)ORD + k) * BB + b];

    #pragma unroll
    for (int m = 0; m < NCH - 1; m++) {
        float ns[ORD];
        #pragma unroll
        for (int k = 0; k < ORD; k++) ns[k] = va[k];
        #pragma unroll
        for (int k = 0; k < ORD; k++) va[k] = vb[k];
        if (m + 2 <= NCH - 2) {
            const float* gv = g_v + ((size_t)(m + 2) * ORD) * BB + b;
            #pragma unroll
            for (int k = 0; k < ORD; k++) vb[k] = gv[(size_t)k * BB];
        }
        #pragma unroll
        for (int r = 0; r < ORD; r++) {
            float sr = s[r];
            #pragma unroll
            for (int k = 0; k < ORD; k++) ns[k] += MT[r * ORD + k] * sr;
        }
        float* gs = g_s + ((size_t)(m + 1) * ORD) * BB + b;
        #pragma unroll
        for (int k = 0; k < ORD; k++) { s[k] = ns[k]; gs[(size_t)k * BB] = s[k]; }
    }
}

// ---------------------------------------------------------------------------
// Kernel 3 (pass2): true-state replay (r7 compute path) with 32-step smem
// staging; flush = one warp writes one row x 32 contiguous cols (128B run),
// cutting out-write sector amplification 1.5x -> 1.25x.
// ---------------------------------------------------------------------------
__global__ void __launch_bounds__(BT) pass2_kernel(const float* __restrict__ u,
                                                   const float* __restrict__ W,
                                                   float* __restrict__ out) {
    __shared__ float su[BT][41];
    __shared__ float sb[32][BT + 1];       // 32-step staging (16.5 KB)
    int m  = blockIdx.x >> 5;
    int b0 = (blockIdx.x & 31) * BT;
    int tid = threadIdx.x;
    int lane = tid & 31, wr = tid >> 5;
    int ocol0 = ORD + m * KC;

    float a[ORD], wu[EX];
    load_a(W, a);
    #pragma unroll
    for (int e = 0; e < EX; e++) wu[e] = __ldg(&W[8 + e]);

    load_utile(u, su, b0, m, 0, lane, wr);
    __syncthreads();

    float w[ORD], uw[ORD];
    const float* gs = g_s + ((size_t)m * ORD) * BB + b0 + tid;
    #pragma unroll
    for (int k = 0; k < ORD; k++) { w[k] = gs[(size_t)k * BB]; uw[k] = su[tid][k]; }

    // Steps 0..31 (phase A), staged into sb[0..31]
    #pragma unroll
    for (int j = 0; j < 32; j++) {
        float x = step_rec(a, wu, uw, w, j);
        if (j <= 29) uw[j % 9] = su[tid][j + 9];
        w[j % 9] = x;
        sb[j][tid] = x;
    }

    // Flush steps 0..31: warp q-row mapping -> one 128B run per warp.
    __syncthreads();
    #pragma unroll
    for (int q = 0; q < 32; q++) {
        int e  = q * BT + tid;
        int cp = e & 31;          // col within group (lane)
        int rp = e >> 5;          // row 0..127
        out[(size_t)(b0 + rp) * OUTW + ocol0 + cp] = sb[cp][rp];
    }
    __syncthreads();

    load_utile(u, su, b0, m, 32, lane, wr);
    __syncthreads();
    uw[30 % 9] = su[tid][7];   // col 39
    uw[31 % 9] = su[tid][8];   // col 40

    // Steps 32..63 (phase B)
    #pragma unroll
    for (int j = 32; j < KC; j++) {
        float x = step_rec(a, wu, uw, w, j);
        if (j <= 61) uw[j % 9] = su[tid][j - 23];
        w[j % 9] = x;
        sb[j - 32][tid] = x;
    }

    __syncthreads();
    #pragma unroll
    for (int q = 0; q < 32; q++) {
        int e  = q * BT + tid;
        int cp = e & 31;
        int rp = e >> 5;
        out[(size_t)(b0 + rp) * OUTW + ocol0 + 32 + cp] = sb[cp][rp];
    }
}

// ---------------------------------------------------------------------------
extern "C" void kernel_launch(void* const* d_in, const int* in_sizes, int n_in,
                              void* d_out, int out_size) {
    const float* y = (const float*)d_in[0];
    const float* u = (const float*)d_in[1];
    const float* W = (const float*)d_in[2];
    for (int i = 0; i < n_in; i++) {
        if (in_sizes[i] == BB * ORD)      y = (const float*)d_in[i];
        else if (in_sizes[i] == BB * SU)  u = (const float*)d_in[i];
        else if (in_sizes[i] == 16)       W = (const float*)d_in[i];
    }
    float* out = (float*)d_out;

    cudaFuncSetAttribute(cv_kernel,    cudaFuncAttributePreferredSharedMemoryCarveout, 100);
    cudaFuncSetAttribute(pass2_kernel, cudaFuncAttributePreferredSharedMemoryCarveout, 100);

    cv_kernel<<<NCH * (BB / BT), BT>>>(u, W);       // 1024 x 128
    states_kernel<<<BB / 32, 32>>>(W, y, out);      // 128 x 32
    pass2_kernel<<<NCH * (BB / BT), BT>>>(u, W, out);
}